// round 2
// baseline (speedup 1.0000x reference)
#include <cuda_runtime.h>
#include <cuda_bf16.h>

// Problem shape (fixed by the dataset)
#define BB 8
#define MM 2048
#define NN 2048
#define KK 2048
#define T64 64
#define MT (MM / T64)   // 32
#define KT (KK / T64)   // 32
#define THRESH 1e-6f

// Activity mask for A's 64x64 tiles: 1.0f if max|a| > THRESH else 0.0f
__device__ float d_mask[BB * MT * KT];

// ---------------------------------------------------------------------------
// Kernel 1: activity prescan. One block per (b, mt, kt) tile; 256 threads
// reduce 4096 elements.
// ---------------------------------------------------------------------------
__global__ void prescan_kernel(const float* __restrict__ a) {
    const int tile = blockIdx.x;            // 0 .. BB*MT*KT-1
    const int b    = tile / (MT * KT);
    const int rem  = tile % (MT * KT);
    const int mt   = rem / KT;
    const int kt   = rem % KT;

    const float* base = a + ((long)b * MM + (long)mt * T64) * KK + (long)kt * T64;

    float mx = 0.0f;
    #pragma unroll 4
    for (int i = threadIdx.x; i < T64 * T64; i += 256) {
        const int r = i >> 6;
        const int c = i & 63;
        mx = fmaxf(mx, fabsf(base[(long)r * KK + c]));
    }

    // warp reduce
    #pragma unroll
    for (int off = 16; off > 0; off >>= 1)
        mx = fmaxf(mx, __shfl_xor_sync(0xFFFFFFFFu, mx, off));

    __shared__ float s[8];
    if ((threadIdx.x & 31) == 0) s[threadIdx.x >> 5] = mx;
    __syncthreads();
    if (threadIdx.x == 0) {
        float m = s[0];
        #pragma unroll
        for (int w = 1; w < 8; w++) m = fmaxf(m, s[w]);
        d_mask[tile] = (m > THRESH) ? 1.0f : 0.0f;
    }
}

// ---------------------------------------------------------------------------
// Kernel 2: 128x128x8 double-buffered SGEMM, 8x8 per thread, mask applied to
// A at the shared-store stage.
// ---------------------------------------------------------------------------
#define BM 128
#define BN 128
#define BK 8
#define TM 8
#define TN 8

__global__ __launch_bounds__(256, 2)
void sgemm_masked_kernel(const float* __restrict__ A,
                         const float* __restrict__ Bg,
                         float* __restrict__ C) {
    const int b  = blockIdx.z;
    const int bm = blockIdx.y;
    const int bn = blockIdx.x;

    const float* Ab = A  + (long)b * MM * KK + (long)bm * BM * KK;
    const float* Bb = Bg + (long)b * KK * NN + (long)bn * BN;
    float*       Cb = C  + (long)b * MM * NN + (long)bm * BM * NN + (long)bn * BN;
    const float* maskRow = d_mask + b * (MT * KT);

    __shared__ float As[2][BK][BM];   // transposed A tile
    __shared__ float Bs[2][BK][BN];

    const int tid = threadIdx.x;

    // A tile load mapping: 128 rows x 8 cols; each thread loads one float4
    const int arow = tid >> 1;            // 0..127
    const int acol = (tid & 1) * 4;       // 0 or 4
    // B tile load mapping: 8 rows x 128 cols; one float4 per thread
    const int brow = tid >> 5;            // 0..7
    const int bcol = (tid & 31) * 4;      // 0..124

    // compute mapping: 16x16 thread grid, each does TMxTN
    const int tx = tid & 15;
    const int ty = tid >> 4;

    // m64 tile row for this thread's A-load row (fixed)
    const int mtbase = ((bm * BM + arow) >> 6) * KT;

    float acc[TM][TN];
    #pragma unroll
    for (int i = 0; i < TM; i++)
        #pragma unroll
        for (int j = 0; j < TN; j++) acc[i][j] = 0.0f;

    // ---- prologue: load tile k0 = 0 into buffer 0
    {
        const float msk = maskRow[0];  // (0 >> 6) == 0
        float4 va = *(const float4*)(Ab + (long)arow * KK + acol);
        As[0][acol + 0][arow] = va.x * msk;
        As[0][acol + 1][arow] = va.y * msk;
        As[0][acol + 2][arow] = va.z * msk;
        As[0][acol + 3][arow] = va.w * msk;
        float4 vb = *(const float4*)(Bb + (long)brow * NN + bcol);
        *(float4*)&Bs[0][brow][bcol] = vb;
    }
    __syncthreads();

    int buf = 0;
    for (int k0 = 0; k0 < KK; k0 += BK) {
        const int knext = k0 + BK;
        float4 pa, pb;
        float  msk = 0.0f;
        const bool have_next = (knext < KK);

        // prefetch next tile into registers (overlaps with FMA burst below)
        if (have_next) {
            pa  = *(const float4*)(Ab + (long)arow * KK + knext + acol);
            pb  = *(const float4*)(Bb + (long)(knext + brow) * NN + bcol);
            msk = maskRow[mtbase + (knext >> 6)];
        }

        // compute current buffer
        #pragma unroll
        for (int kk = 0; kk < BK; kk++) {
            float4 a0 = *(const float4*)&As[buf][kk][ty * TM];
            float4 a1 = *(const float4*)&As[buf][kk][ty * TM + 4];
            float4 b0 = *(const float4*)&Bs[buf][kk][tx * TN];
            float4 b1 = *(const float4*)&Bs[buf][kk][tx * TN + 4];
            const float ar[TM] = {a0.x, a0.y, a0.z, a0.w, a1.x, a1.y, a1.z, a1.w};
            const float br[TN] = {b0.x, b0.y, b0.z, b0.w, b1.x, b1.y, b1.z, b1.w};
            #pragma unroll
            for (int i = 0; i < TM; i++)
                #pragma unroll
                for (int j = 0; j < TN; j++)
                    acc[i][j] = fmaf(ar[i], br[j], acc[i][j]);
        }

        // stage prefetched data into the other buffer
        if (have_next) {
            const int nb = buf ^ 1;
            As[nb][acol + 0][arow] = pa.x * msk;
            As[nb][acol + 1][arow] = pa.y * msk;
            As[nb][acol + 2][arow] = pa.z * msk;
            As[nb][acol + 3][arow] = pa.w * msk;
            *(float4*)&Bs[nb][brow][bcol] = pb;
        }
        __syncthreads();
        buf ^= 1;
    }

    // ---- epilogue: write 8x8 block with float4 stores
    #pragma unroll
    for (int i = 0; i < TM; i++) {
        float* crow = Cb + (long)(ty * TM + i) * NN + tx * TN;
        float4 o0 = make_float4(acc[i][0], acc[i][1], acc[i][2], acc[i][3]);
        float4 o1 = make_float4(acc[i][4], acc[i][5], acc[i][6], acc[i][7]);
        *(float4*)(crow + 0) = o0;
        *(float4*)(crow + 4) = o1;
    }
}

// ---------------------------------------------------------------------------
// Launch
// ---------------------------------------------------------------------------
extern "C" void kernel_launch(void* const* d_in, const int* in_sizes, int n_in,
                              void* d_out, int out_size) {
    const float* a = (const float*)d_in[0];
    const float* b = (const float*)d_in[1];
    float* out = (float*)d_out;

    // 1) activity prescan over A's 64x64 tiles
    prescan_kernel<<<BB * MT * KT, 256>>>(a);

    // 2) masked SGEMM
    dim3 grid(NN / BN, MM / BM, BB);   // (16, 16, 8)
    sgemm_masked_kernel<<<grid, 256>>>(a, b, out);
}

// round 4
// speedup vs baseline: 1.4143x; 1.4143x over previous
#include <cuda_runtime.h>
#include <cuda_bf16.h>
#include <cstdint>

// ---------------------------------------------------------------------------
// Problem shape (fixed by the dataset)
// ---------------------------------------------------------------------------
#define BB 8
#define MM 2048
#define NN 2048
#define KK 2048
#define T64 64
#define MT 32
#define KT 32
#define THRESH 1e-6f

// ---------------------------------------------------------------------------
// Scratch (device globals — no allocation allowed)
// ---------------------------------------------------------------------------
__device__ float d_mask[BB * MT * KT];
__device__ __nv_bfloat16 g_Ahi[(size_t)BB * MM * KK];   // [b][m][k]
__device__ __nv_bfloat16 g_Alo[(size_t)BB * MM * KK];
__device__ __nv_bfloat16 g_Bhi[(size_t)BB * NN * KK];   // transposed: [b][n][k]
__device__ __nv_bfloat16 g_Blo[(size_t)BB * NN * KK];

// ---------------------------------------------------------------------------
// Helpers
// ---------------------------------------------------------------------------
__device__ __forceinline__ uint32_t smem_u32(const void* p) {
    uint32_t a;
    asm("{ .reg .u64 t; cvta.to.shared.u64 t, %1; cvt.u32.u64 %0, t; }" : "=r"(a) : "l"(p));
    return a;
}
__device__ __forceinline__ void cp16(uint32_t dst, const void* src) {
    asm volatile("cp.async.cg.shared.global [%0], [%1], 16;" :: "r"(dst), "l"(src));
}
#define SMEM_SWIZZLE_128B(off) ((off) ^ (((off) >> 3) & 0x70))

__device__ __forceinline__ void ldsm_x4(uint32_t r[4], uint32_t addr) {
    asm volatile("ldmatrix.sync.aligned.m8n8.x4.shared.b16 {%0,%1,%2,%3}, [%4];"
                 : "=r"(r[0]), "=r"(r[1]), "=r"(r[2]), "=r"(r[3]) : "r"(addr));
}
__device__ __forceinline__ void mma_bf16(float c[4], const uint32_t a[4],
                                         uint32_t b0, uint32_t b1) {
    asm volatile(
        "mma.sync.aligned.m16n8k16.row.col.f32.bf16.bf16.f32 "
        "{%0,%1,%2,%3}, {%4,%5,%6,%7}, {%8,%9}, {%0,%1,%2,%3};"
        : "+f"(c[0]), "+f"(c[1]), "+f"(c[2]), "+f"(c[3])
        : "r"(a[0]), "r"(a[1]), "r"(a[2]), "r"(a[3]), "r"(b0), "r"(b1));
}

// ---------------------------------------------------------------------------
// Kernel 1: activity prescan (one block per 64x64 tile of A)
// ---------------------------------------------------------------------------
__global__ void prescan_kernel(const float* __restrict__ a) {
    const int tile = blockIdx.x;
    const int b    = tile / (MT * KT);
    const int rem  = tile % (MT * KT);
    const int mt   = rem / KT;
    const int kt   = rem % KT;
    const float* base = a + ((size_t)b * MM + (size_t)mt * T64) * KK + (size_t)kt * T64;

    float mx = 0.0f;
    #pragma unroll 4
    for (int i = threadIdx.x; i < T64 * T64; i += 256) {
        const int r = i >> 6, c = i & 63;
        mx = fmaxf(mx, fabsf(base[(size_t)r * KK + c]));
    }
    #pragma unroll
    for (int off = 16; off > 0; off >>= 1)
        mx = fmaxf(mx, __shfl_xor_sync(0xFFFFFFFFu, mx, off));
    __shared__ float s[8];
    if ((threadIdx.x & 31) == 0) s[threadIdx.x >> 5] = mx;
    __syncthreads();
    if (threadIdx.x == 0) {
        float m = s[0];
        #pragma unroll
        for (int w = 1; w < 8; w++) m = fmaxf(m, s[w]);
        d_mask[tile] = (m > THRESH) ? 1.0f : 0.0f;
    }
}

// ---------------------------------------------------------------------------
// Kernel 2: convert A -> masked bf16 hi/lo (same [b][m][k] layout)
// ---------------------------------------------------------------------------
__global__ void convA_kernel(const float* __restrict__ a) {
    const size_t total4 = (size_t)BB * MM * KK / 4;
    for (size_t i = (size_t)blockIdx.x * blockDim.x + threadIdx.x; i < total4;
         i += (size_t)gridDim.x * blockDim.x) {
        const size_t e = i * 4;
        const int b   = (int)(e >> 22);          // MM*KK = 2^22
        const int rem = (int)(e & 0x3FFFFF);
        const int m   = rem >> 11;               // KK = 2^11
        const int k   = rem & 2047;
        const float msk = d_mask[b * (MT * KT) + (m >> 6) * KT + (k >> 6)];

        float4 v = reinterpret_cast<const float4*>(a)[i];
        float f[4] = {v.x * msk, v.y * msk, v.z * msk, v.w * msk};

        unsigned short hb[4], lb[4];
        #pragma unroll
        for (int j = 0; j < 4; j++) {
            __nv_bfloat16 h = __float2bfloat16_rn(f[j]);
            __nv_bfloat16 l = __float2bfloat16_rn(f[j] - __bfloat162float(h));
            hb[j] = *reinterpret_cast<unsigned short*>(&h);
            lb[j] = *reinterpret_cast<unsigned short*>(&l);
        }
        reinterpret_cast<ushort4*>(g_Ahi)[i] = make_ushort4(hb[0], hb[1], hb[2], hb[3]);
        reinterpret_cast<ushort4*>(g_Alo)[i] = make_ushort4(lb[0], lb[1], lb[2], lb[3]);
    }
}

// ---------------------------------------------------------------------------
// Kernel 3: convert + transpose B: fp32 [b][k][n] -> bf16 hi/lo [b][n][k]
// ---------------------------------------------------------------------------
__global__ void convB_kernel(const float* __restrict__ Bsrc) {
    __shared__ float t[32][33];
    const int b  = blockIdx.z;
    const int n0 = blockIdx.x * 32;
    const int k0 = blockIdx.y * 32;
    const int tx = threadIdx.x & 31;
    const int ty = threadIdx.x >> 5;     // 0..7

    const float* src = Bsrc + (size_t)b * KK * NN;
    #pragma unroll
    for (int r = 0; r < 32; r += 8)
        t[ty + r][tx] = src[(size_t)(k0 + ty + r) * NN + n0 + tx];
    __syncthreads();

    const size_t dst = (size_t)b * NN * KK;
    #pragma unroll
    for (int r = 0; r < 32; r += 8) {
        const float v = t[tx][ty + r];
        __nv_bfloat16 h = __float2bfloat16_rn(v);
        __nv_bfloat16 l = __float2bfloat16_rn(v - __bfloat162float(h));
        const size_t o = dst + (size_t)(n0 + ty + r) * KK + k0 + tx;
        g_Bhi[o] = h;
        g_Blo[o] = l;
    }
}

// ---------------------------------------------------------------------------
// Kernel 4: bf16 split-3 GEMM via mma.sync (m16n8k16).
//   CTA tile 128(M) x 128(N), K-chunk 64 bf16, 8 warps (2x4), warp tile 64x32.
// ---------------------------------------------------------------------------
#define GM 128
#define GN 128
#define GK 64
#define KCHUNKS (KK / GK)            // 32

// SMEM stage layout: 4 arrays of [128 rows][128 bytes] (SW128 swizzled)
#define OFF_AHI 0
#define OFF_ALO 16384
#define OFF_BHI 32768
#define OFF_BLO 49152
#define STAGE_BYTES 65536
#define GEMM_SMEM (2 * STAGE_BYTES)  // 131072

__device__ __forceinline__ void load_stage(uint32_t sbase,
                                           const __nv_bfloat16* Ah, const __nv_bfloat16* Al,
                                           const __nv_bfloat16* Bh, const __nv_bfloat16* Bl,
                                           int k0, int tid) {
    // each array: 128 rows x 8 x 16B chunks = 1024 chunks; 4 per thread per array
    #pragma unroll
    for (int t = 0; t < 4; t++) {
        const int c = tid + t * 256;
        const int r = c >> 3, kc = c & 7;
        const uint32_t off = SMEM_SWIZZLE_128B((uint32_t)(r * 128 + kc * 16));
        const size_t gofs = (size_t)r * KK + k0 + kc * 8;   // bf16 elements
        cp16(sbase + OFF_AHI + off, Ah + gofs);
        cp16(sbase + OFF_ALO + off, Al + gofs);
        cp16(sbase + OFF_BHI + off, Bh + gofs);
        cp16(sbase + OFF_BLO + off, Bl + gofs);
    }
}

__global__ __launch_bounds__(256)
void gemm_kernel(float* __restrict__ C) {
    extern __shared__ __align__(1024) char smem[];
    const uint32_t sb = smem_u32(smem);
    const int tid  = threadIdx.x;
    const int wid  = tid >> 5;
    const int lane = tid & 31;
    const int wm   = wid >> 2;           // 0..1  -> m offset wm*64
    const int wn   = wid & 3;            // 0..3  -> n offset wn*32
    const int b  = blockIdx.z;
    const int m0 = blockIdx.y * GM;
    const int n0 = blockIdx.x * GN;

    const __nv_bfloat16* Ah = g_Ahi + (size_t)b * MM * KK + (size_t)m0 * KK;
    const __nv_bfloat16* Al = g_Alo + (size_t)b * MM * KK + (size_t)m0 * KK;
    const __nv_bfloat16* Bh = g_Bhi + (size_t)b * NN * KK + (size_t)n0 * KK;
    const __nv_bfloat16* Bl = g_Blo + (size_t)b * NN * KK + (size_t)n0 * KK;

    float acc[4][4][4];                  // [m-tile][n-tile][frag]
    #pragma unroll
    for (int i = 0; i < 4; i++)
        #pragma unroll
        for (int j = 0; j < 4; j++)
            #pragma unroll
            for (int r = 0; r < 4; r++) acc[i][j][r] = 0.0f;

    // ldmatrix per-thread row index within tile group (lane&15) + hi/lo chunk (lane>>4)
    const int lrow = lane & 15;
    const int lhalf = lane >> 4;         // 0/1 -> +0 / +8 k-elements (16B)

    // prologue: chunks 0 and 1
    load_stage(sb,               Ah, Al, Bh, Bl, 0,  tid);
    asm volatile("cp.async.commit_group;" ::: "memory");
    load_stage(sb + STAGE_BYTES, Ah, Al, Bh, Bl, GK, tid);
    asm volatile("cp.async.commit_group;" ::: "memory");

    for (int it = 0; it < KCHUNKS; it++) {
        const uint32_t sbase = sb + (it & 1) * STAGE_BYTES;

        if (it < KCHUNKS - 1) asm volatile("cp.async.wait_group 1;" ::: "memory");
        else                  asm volatile("cp.async.wait_group 0;" ::: "memory");
        __syncthreads();

        #pragma unroll
        for (int ks = 0; ks < 4; ks++) {     // 4 x k16 steps per 64-chunk
            const uint32_t bytecol = (uint32_t)(ks * 32 + lhalf * 16);

            uint32_t ahi[4][4], alo[4][4];
            #pragma unroll
            for (int mt = 0; mt < 4; mt++) {
                const uint32_t row = (uint32_t)(wm * 64 + mt * 16 + lrow);
                const uint32_t off = SMEM_SWIZZLE_128B(row * 128 + bytecol);
                ldsm_x4(ahi[mt], sbase + OFF_AHI + off);
                ldsm_x4(alo[mt], sbase + OFF_ALO + off);
            }
            uint32_t bhi[2][4], blo[2][4];
            #pragma unroll
            for (int nt2 = 0; nt2 < 2; nt2++) {
                const uint32_t row = (uint32_t)(wn * 32 + nt2 * 16 + lrow);
                const uint32_t off = SMEM_SWIZZLE_128B(row * 128 + bytecol);
                ldsm_x4(bhi[nt2], sbase + OFF_BHI + off);
                ldsm_x4(blo[nt2], sbase + OFF_BLO + off);
            }

            // x4 B regs: {r0,r2} = n-tile (nt2*2), {r1,r3} = n-tile (nt2*2+1)
            #pragma unroll
            for (int mt = 0; mt < 4; mt++) {
                #pragma unroll
                for (int nt2 = 0; nt2 < 2; nt2++) {
                    mma_bf16(acc[mt][nt2 * 2 + 0], ahi[mt], bhi[nt2][0], bhi[nt2][2]);
                    mma_bf16(acc[mt][nt2 * 2 + 1], ahi[mt], bhi[nt2][1], bhi[nt2][3]);
                    mma_bf16(acc[mt][nt2 * 2 + 0], ahi[mt], blo[nt2][0], blo[nt2][2]);
                    mma_bf16(acc[mt][nt2 * 2 + 1], ahi[mt], blo[nt2][1], blo[nt2][3]);
                    mma_bf16(acc[mt][nt2 * 2 + 0], alo[mt], bhi[nt2][0], bhi[nt2][2]);
                    mma_bf16(acc[mt][nt2 * 2 + 1], alo[mt], bhi[nt2][1], bhi[nt2][3]);
                }
            }
        }
        __syncthreads();

        if (it + 2 < KCHUNKS) {
            load_stage(sbase, Ah, Al, Bh, Bl, (it + 2) * GK, tid);
            asm volatile("cp.async.commit_group;" ::: "memory");
        }
    }

    // epilogue: c frag -> rows (lane>>2) and +8, cols (lane&3)*2..+1
    const int crow0 = m0 + wm * 64 + (lane >> 2);
    const int ccol0 = n0 + wn * 32 + (lane & 3) * 2;
    float* Cb = C + (size_t)b * MM * NN;
    #pragma unroll
    for (int mt = 0; mt < 4; mt++) {
        #pragma unroll
        for (int nt = 0; nt < 4; nt++) {
            float* p0 = Cb + (size_t)(crow0 + mt * 16) * NN + ccol0 + nt * 8;
            float* p1 = p0 + 8 * NN;
            *reinterpret_cast<float2*>(p0) = make_float2(acc[mt][nt][0], acc[mt][nt][1]);
            *reinterpret_cast<float2*>(p1) = make_float2(acc[mt][nt][2], acc[mt][nt][3]);
        }
    }
}

// ---------------------------------------------------------------------------
// Launch
// ---------------------------------------------------------------------------
extern "C" void kernel_launch(void* const* d_in, const int* in_sizes, int n_in,
                              void* d_out, int out_size) {
    const float* a = (const float*)d_in[0];
    const float* bsrc = (const float*)d_in[1];
    float* out = (float*)d_out;

    cudaFuncSetAttribute(gemm_kernel, cudaFuncAttributeMaxDynamicSharedMemorySize, GEMM_SMEM);

    prescan_kernel<<<BB * MT * KT, 256>>>(a);
    convA_kernel<<<8192, 256>>>(a);
    dim3 gb(NN / 32, KK / 32, BB);          // (64, 64, 8)
    convB_kernel<<<gb, 256>>>(bsrc);
    dim3 gg(NN / GN, MM / GM, BB);          // (16, 16, 8)
    gemm_kernel<<<gg, 256, GEMM_SMEM>>>(out);
}

// round 7
// speedup vs baseline: 2.5737x; 1.8197x over previous
#include <cuda_runtime.h>
#include <cuda_bf16.h>
#include <cstdint>

// ---------------------------------------------------------------------------
// Problem shape (fixed by the dataset)
// ---------------------------------------------------------------------------
#define BB 8
#define MM 2048
#define NN 2048
#define KK 2048
#define T64 64
#define MT 32
#define KT 32
#define THRESH 1e-6f

// ---------------------------------------------------------------------------
// Scratch (device globals — no allocation allowed)
// ---------------------------------------------------------------------------
__device__ __nv_bfloat16 g_Ahi[(size_t)BB * MM * KK];   // [b][m][k]
__device__ __nv_bfloat16 g_Alo[(size_t)BB * MM * KK];
__device__ __nv_bfloat16 g_Bhi[(size_t)BB * NN * KK];   // transposed: [b][n][k]
__device__ __nv_bfloat16 g_Blo[(size_t)BB * NN * KK];

// ---------------------------------------------------------------------------
// Helpers
// ---------------------------------------------------------------------------
__device__ __forceinline__ uint32_t smem_u32(const void* p) {
    uint32_t a;
    asm("{ .reg .u64 t; cvta.to.shared.u64 t, %1; cvt.u32.u64 %0, t; }" : "=r"(a) : "l"(p));
    return a;
}
__device__ __forceinline__ void cp16(uint32_t dst, const void* src) {
    asm volatile("cp.async.cg.shared.global [%0], [%1], 16;" :: "r"(dst), "l"(src));
}
// 64-byte-row swizzle (SW64): XOR bits[5:4] with bits[8:7]
#define SMEM_SWIZZLE_64B(off) ((off) ^ (((off) >> 3) & 0x30))

__device__ __forceinline__ void ldsm_x4(uint32_t r[4], uint32_t addr) {
    asm volatile("ldmatrix.sync.aligned.m8n8.x4.shared.b16 {%0,%1,%2,%3}, [%4];"
                 : "=r"(r[0]), "=r"(r[1]), "=r"(r[2]), "=r"(r[3]) : "r"(addr));
}
__device__ __forceinline__ void mma_bf16(float c[4], const uint32_t a[4],
                                         uint32_t b0, uint32_t b1) {
    asm volatile(
        "mma.sync.aligned.m16n8k16.row.col.f32.bf16.bf16.f32 "
        "{%0,%1,%2,%3}, {%4,%5,%6,%7}, {%8,%9}, {%0,%1,%2,%3};"
        : "+f"(c[0]), "+f"(c[1]), "+f"(c[2]), "+f"(c[3])
        : "r"(a[0]), "r"(a[1]), "r"(a[2]), "r"(a[3]), "r"(b0), "r"(b1));
}

// ---------------------------------------------------------------------------
// Kernel 1: fused activity prescan + A conversion.
//   One block per 64x64 tile: load tile to regs, block max-reduce |a|,
//   then mask + bf16 hi/lo split + store.  Reads A exactly once.
// ---------------------------------------------------------------------------
__global__ __launch_bounds__(256)
void convA_fused_kernel(const float* __restrict__ a) {
    const int tile = blockIdx.x;
    const int b    = tile / (MT * KT);
    const int rem  = tile % (MT * KT);
    const int mt   = rem / KT;
    const int kt   = rem % KT;
    const size_t gbase = ((size_t)b * MM + (size_t)mt * T64) * KK + (size_t)kt * T64;
    const float* base = a + gbase;

    const int r0 = threadIdx.x >> 4;          // 0..15
    const int c0 = (threadIdx.x & 15) * 4;    // 0..60

    float4 v[4];
    float mx = 0.0f;
    #pragma unroll
    for (int j = 0; j < 4; j++) {
        v[j] = *reinterpret_cast<const float4*>(base + (size_t)(r0 + j * 16) * KK + c0);
        mx = fmaxf(mx, fmaxf(fmaxf(fabsf(v[j].x), fabsf(v[j].y)),
                             fmaxf(fabsf(v[j].z), fabsf(v[j].w))));
    }
    #pragma unroll
    for (int off = 16; off > 0; off >>= 1)
        mx = fmaxf(mx, __shfl_xor_sync(0xFFFFFFFFu, mx, off));

    __shared__ float s[8];
    __shared__ float s_msk;
    if ((threadIdx.x & 31) == 0) s[threadIdx.x >> 5] = mx;
    __syncthreads();
    if (threadIdx.x == 0) {
        float m = s[0];
        #pragma unroll
        for (int w = 1; w < 8; w++) m = fmaxf(m, s[w]);
        s_msk = (m > THRESH) ? 1.0f : 0.0f;
    }
    __syncthreads();
    const float msk = s_msk;

    #pragma unroll
    for (int j = 0; j < 4; j++) {
        float f[4] = {v[j].x * msk, v[j].y * msk, v[j].z * msk, v[j].w * msk};
        unsigned short hb[4], lb[4];
        #pragma unroll
        for (int q = 0; q < 4; q++) {
            __nv_bfloat16 h = __float2bfloat16_rn(f[q]);
            __nv_bfloat16 l = __float2bfloat16_rn(f[q] - __bfloat162float(h));
            hb[q] = *reinterpret_cast<unsigned short*>(&h);
            lb[q] = *reinterpret_cast<unsigned short*>(&l);
        }
        const size_t o = gbase + (size_t)(r0 + j * 16) * KK + c0;
        *reinterpret_cast<ushort4*>(g_Ahi + o) = make_ushort4(hb[0], hb[1], hb[2], hb[3]);
        *reinterpret_cast<ushort4*>(g_Alo + o) = make_ushort4(lb[0], lb[1], lb[2], lb[3]);
    }
}

// ---------------------------------------------------------------------------
// Kernel 2: convert + transpose B: fp32 [b][k][n] -> bf16 hi/lo [b][n][k]
// ---------------------------------------------------------------------------
__global__ void convB_kernel(const float* __restrict__ Bsrc) {
    __shared__ float t[32][33];
    const int b  = blockIdx.z;
    const int n0 = blockIdx.x * 32;
    const int k0 = blockIdx.y * 32;
    const int tx = threadIdx.x & 31;
    const int ty = threadIdx.x >> 5;     // 0..7

    const float* src = Bsrc + (size_t)b * KK * NN;
    #pragma unroll
    for (int r = 0; r < 32; r += 8)
        t[ty + r][tx] = src[(size_t)(k0 + ty + r) * NN + n0 + tx];
    __syncthreads();

    const size_t dst = (size_t)b * NN * KK;
    #pragma unroll
    for (int r = 0; r < 32; r += 8) {
        const float v = t[tx][ty + r];
        __nv_bfloat16 h = __float2bfloat16_rn(v);
        __nv_bfloat16 l = __float2bfloat16_rn(v - __bfloat162float(h));
        const size_t o = dst + (size_t)(n0 + ty + r) * KK + k0 + tx;
        g_Bhi[o] = h;
        g_Blo[o] = l;
    }
}

// ---------------------------------------------------------------------------
// Kernel 3: bf16 split-3 GEMM via mma.sync (m16n8k16).
//   CTA tile 128(M) x 128(N), K-chunk 32, 8 warps (2x4), warp tile 64x32.
//   3-stage cp.async pipeline, 32 KB/stage -> 96 KB smem -> 2 CTAs/SM.
// ---------------------------------------------------------------------------
#define GM 128
#define GN 128
#define GK 32
#define KCHUNKS (KK / GK)            // 64
#define NSTAGE 3

// Stage layout (SW64-swizzled 64-byte rows):
//   AHI [128][64B], ALO [128][64B], BHI [128][64B], BLO [128][64B]
#define OFF_AHI 0
#define OFF_ALO 8192
#define OFF_BHI 16384
#define OFF_BLO 24576
#define STAGE_BYTES 32768            // 32 KB
#define GEMM_SMEM (NSTAGE * STAGE_BYTES)  // 96 KB

__device__ __forceinline__ void load_stage(uint32_t sbase,
                                           const __nv_bfloat16* Ah, const __nv_bfloat16* Al,
                                           const __nv_bfloat16* Bh, const __nv_bfloat16* Bl,
                                           int k0, int tid) {
    // each array: 128 rows x 4 x 16B chunks = 512 chunks; 2 per thread per array
    #pragma unroll
    for (int t = 0; t < 2; t++) {
        const int c = tid + t * 256;
        const int r = c >> 2, kc = c & 3;
        const uint32_t off = SMEM_SWIZZLE_64B((uint32_t)(r * 64 + kc * 16));
        const size_t gofs = (size_t)r * KK + k0 + kc * 8;    // bf16 elements
        cp16(sbase + OFF_AHI + off, Ah + gofs);
        cp16(sbase + OFF_ALO + off, Al + gofs);
        cp16(sbase + OFF_BHI + off, Bh + gofs);
        cp16(sbase + OFF_BLO + off, Bl + gofs);
    }
}

__global__ __launch_bounds__(256, 2)
void gemm_kernel(float* __restrict__ C) {
    extern __shared__ __align__(1024) char smem[];
    const uint32_t sb = smem_u32(smem);
    const int tid  = threadIdx.x;
    const int wid  = tid >> 5;
    const int lane = tid & 31;
    const int wm   = wid >> 2;           // 0..1  -> m offset wm*64
    const int wn   = wid & 3;            // 0..3  -> n offset wn*32
    const int b  = blockIdx.z;
    const int m0 = blockIdx.y * GM;
    const int n0 = blockIdx.x * GN;

    const __nv_bfloat16* Ah = g_Ahi + (size_t)b * MM * KK + (size_t)m0 * KK;
    const __nv_bfloat16* Al = g_Alo + (size_t)b * MM * KK + (size_t)m0 * KK;
    const __nv_bfloat16* Bh = g_Bhi + (size_t)b * NN * KK + (size_t)n0 * KK;
    const __nv_bfloat16* Bl = g_Blo + (size_t)b * NN * KK + (size_t)n0 * KK;

    float acc[4][4][4];                  // [m-tile][n-tile][frag]
    #pragma unroll
    for (int i = 0; i < 4; i++)
        #pragma unroll
        for (int j = 0; j < 4; j++)
            #pragma unroll
            for (int r = 0; r < 4; r++) acc[i][j][r] = 0.0f;

    const int lrow  = lane & 15;
    const int lhalf = lane >> 4;         // 0/1 -> +0 / +8 k-elements (16B)

    // prologue: fill all three stages
    load_stage(sb + 0 * STAGE_BYTES, Ah, Al, Bh, Bl, 0 * GK, tid);
    asm volatile("cp.async.commit_group;" ::: "memory");
    load_stage(sb + 1 * STAGE_BYTES, Ah, Al, Bh, Bl, 1 * GK, tid);
    asm volatile("cp.async.commit_group;" ::: "memory");
    load_stage(sb + 2 * STAGE_BYTES, Ah, Al, Bh, Bl, 2 * GK, tid);
    asm volatile("cp.async.commit_group;" ::: "memory");

    int stage = 0;
    for (int it = 0; it < KCHUNKS; it++) {
        const uint32_t sbase = sb + stage * STAGE_BYTES;

        if      (it < KCHUNKS - 2) asm volatile("cp.async.wait_group 2;" ::: "memory");
        else if (it == KCHUNKS - 2) asm volatile("cp.async.wait_group 1;" ::: "memory");
        else                        asm volatile("cp.async.wait_group 0;" ::: "memory");
        __syncthreads();

        #pragma unroll
        for (int ks = 0; ks < 2; ks++) {     // 2 x k16 steps per 32-chunk
            const uint32_t bytecol = (uint32_t)(ks * 32 + lhalf * 16);

            uint32_t ahi[4][4], alo[4][4], bb[2][4];
            #pragma unroll
            for (int mt = 0; mt < 4; mt++) {
                const uint32_t off = SMEM_SWIZZLE_64B(
                    (uint32_t)((wm * 64 + mt * 16 + lrow) * 64) + bytecol);
                ldsm_x4(ahi[mt], sbase + OFF_AHI + off);
                ldsm_x4(alo[mt], sbase + OFF_ALO + off);
            }
            #pragma unroll
            for (int nt2 = 0; nt2 < 2; nt2++) {
                const uint32_t off = SMEM_SWIZZLE_64B(
                    (uint32_t)((wn * 32 + nt2 * 16 + lrow) * 64) + bytecol);
                ldsm_x4(bb[nt2], sbase + OFF_BHI + off);
            }

            // product 1: Ahi * Bhi   (16 MMAs, 16 distinct accumulators)
            #pragma unroll
            for (int mt = 0; mt < 4; mt++)
                #pragma unroll
                for (int nt2 = 0; nt2 < 2; nt2++) {
                    mma_bf16(acc[mt][nt2 * 2 + 0], ahi[mt], bb[nt2][0], bb[nt2][2]);
                    mma_bf16(acc[mt][nt2 * 2 + 1], ahi[mt], bb[nt2][1], bb[nt2][3]);
                }
            // product 2: Alo * Bhi
            #pragma unroll
            for (int mt = 0; mt < 4; mt++)
                #pragma unroll
                for (int nt2 = 0; nt2 < 2; nt2++) {
                    mma_bf16(acc[mt][nt2 * 2 + 0], alo[mt], bb[nt2][0], bb[nt2][2]);
                    mma_bf16(acc[mt][nt2 * 2 + 1], alo[mt], bb[nt2][1], bb[nt2][3]);
                }
            // reload B fragments with Blo (reuse registers)
            #pragma unroll
            for (int nt2 = 0; nt2 < 2; nt2++) {
                const uint32_t off = SMEM_SWIZZLE_64B(
                    (uint32_t)((wn * 32 + nt2 * 16 + lrow) * 64) + bytecol);
                ldsm_x4(bb[nt2], sbase + OFF_BLO + off);
            }
            // product 3: Ahi * Blo
            #pragma unroll
            for (int mt = 0; mt < 4; mt++)
                #pragma unroll
                for (int nt2 = 0; nt2 < 2; nt2++) {
                    mma_bf16(acc[mt][nt2 * 2 + 0], ahi[mt], bb[nt2][0], bb[nt2][2]);
                    mma_bf16(acc[mt][nt2 * 2 + 1], ahi[mt], bb[nt2][1], bb[nt2][3]);
                }
        }
        __syncthreads();

        if (it + NSTAGE < KCHUNKS) {
            load_stage(sbase, Ah, Al, Bh, Bl, (it + NSTAGE) * GK, tid);
            asm volatile("cp.async.commit_group;" ::: "memory");
        }
        stage = (stage + 1 == NSTAGE) ? 0 : stage + 1;
    }

    // epilogue: c frag -> rows (lane>>2) and +8, cols (lane&3)*2..+1
    const int crow0 = m0 + wm * 64 + (lane >> 2);
    const int ccol0 = n0 + wn * 32 + (lane & 3) * 2;
    float* Cb = C + (size_t)b * MM * NN;
    #pragma unroll
    for (int mt = 0; mt < 4; mt++) {
        #pragma unroll
        for (int nt = 0; nt < 4; nt++) {
            float* p0 = Cb + (size_t)(crow0 + mt * 16) * NN + ccol0 + nt * 8;
            float* p1 = p0 + 8 * NN;
            *reinterpret_cast<float2*>(p0) = make_float2(acc[mt][nt][0], acc[mt][nt][1]);
            *reinterpret_cast<float2*>(p1) = make_float2(acc[mt][nt][2], acc[mt][nt][3]);
        }
    }
}

// ---------------------------------------------------------------------------
// Launch
// ---------------------------------------------------------------------------
extern "C" void kernel_launch(void* const* d_in, const int* in_sizes, int n_in,
                              void* d_out, int out_size) {
    const float* a = (const float*)d_in[0];
    const float* bsrc = (const float*)d_in[1];
    float* out = (float*)d_out;

    cudaFuncSetAttribute(gemm_kernel, cudaFuncAttributeMaxDynamicSharedMemorySize, GEMM_SMEM);

    convA_fused_kernel<<<BB * MT * KT, 256>>>(a);
    dim3 gb(NN / 32, KK / 32, BB);          // (64, 64, 8)
    convB_kernel<<<gb, 256>>>(bsrc);
    dim3 gg(NN / GN, MM / GM, BB);          // (16, 16, 8)
    gemm_kernel<<<gg, 256, GEMM_SMEM>>>(out);
}